// round 9
// baseline (speedup 1.0000x reference)
#include <cuda_runtime.h>
#include <math.h>

#define BSZ   32
#define AA    8400
#define GG    64
#define NCLS  80
#define TOPK  10
#define EPSV  1e-9f
#define BIGV  100000.0f

// ---------------- scratch (static device memory; no runtime alloc) ----------------
__device__ float              g_delta[(size_t)BSZ * NCLS * AA];  // [b, c, a] = log1p(-p) - log(p)
__device__ float              g_S[BSZ * AA];                     // S[b,a] = -sum_c log1p(-p)
__device__ float              g_atanP[BSZ * AA];                 // atan(w1/h1) (raw)
__device__ int                g_cnt[BSZ * AA];                   // pt_mask count per (b,a)
__device__ unsigned long long g_pick[BSZ * AA];                  // argmin key per (b,a)
__device__ int                g_topidx[BSZ * GG * TOPK];
__device__ float              g_topcost[BSZ * GG * TOPK];

// order-preserving float->uint map (monotone increasing)
__device__ __forceinline__ unsigned encf(float f) {
    unsigned u = __float_as_uint(f);
    unsigned mask = ((unsigned)((int)u >> 31)) | 0x80000000u;
    return u ^ mask;
}
__device__ __forceinline__ float decf(unsigned e) {
    unsigned u = (e & 0x80000000u) ? (e ^ 0x80000000u) : ~e;
    return __uint_as_float(u);
}

// ---------------- K0: init scratch ----------------
__global__ void k0_init() {
    int i = blockIdx.x * blockDim.x + threadIdx.x;
    if (i < BSZ * AA) { g_cnt[i] = 0; g_pick[i] = ~0ull; }
}

// ---------------- K1: per-anchor prep. One WARP per anchor.
// Emulates XLA row-reduce: lane l accumulates classes l, l+32, l+64 (f32, in order),
// then shfl_down tree 16/8/4/2/1. S = -(lane0 result). Coalesced score loads.
__global__ void k1_prep(const float* __restrict__ scores, const float* __restrict__ pboxes) {
    int warp = threadIdx.x >> 5;
    int lane = threadIdx.x & 31;
    int a = blockIdx.x * 8 + warp;     // 8400 = 8 * 1050, exact
    int b = blockIdx.y;

    const float* row = scores + ((size_t)b * AA + a) * NCLS;
    float acc = 0.0f;
#pragma unroll
    for (int j = 0; j < 3; j++) {
        int c = lane + j * 32;
        if (c < NCLS) {
            float p  = fminf(fmaxf(row[c], 1e-7f), 0.99999994f);
            float lp = logf(p);            // libdevice __nv_logf (matches XLA)
            float l1 = log1pf(-p);         // libdevice __nv_log1pf (matches XLA)
            acc = __fadd_rn(acc, l1);
            g_delta[((size_t)b * NCLS + c) * AA + a] = __fsub_rn(l1, lp);
        }
    }
#pragma unroll
    for (int off = 16; off > 0; off >>= 1)
        acc = __fadd_rn(acc, __shfl_down_sync(0xffffffffu, acc, off));

    if (lane == 0) {
        g_S[b * AA + a] = -acc;
        float4 bx = reinterpret_cast<const float4*>(pboxes)[(size_t)b * AA + a];
        float w1 = __fsub_rn(bx.z, bx.x);
        float h1 = __fadd_rn(__fsub_rn(bx.w, bx.y), EPSV);
        g_atanP[b * AA + a] = atanf(__fdiv_rn(w1, h1));
    }
}

// ---------------- K2: cost matrix (bit-faithful f32 emulation of reference) ----------------
__global__ void k2_cost(const float* __restrict__ pboxes, const float* __restrict__ gboxes,
                        const int* __restrict__ glabels, float* __restrict__ costOut) {
    __shared__ float sgx1[GG], sgy1[GG], sgx2[GG], sgy2[GG];
    __shared__ float sglx[GG], sgly[GG], sghx[GG], sghy[GG];
    __shared__ float sgsx[GG], sgsy[GG], swh[GG], sat[GG];
    __shared__ int   slab[GG];

    int b   = blockIdx.y;
    int tid = threadIdx.x;
    if (tid < GG) {
        float4 gb = reinterpret_cast<const float4*>(gboxes)[b * GG + tid];
        sgx1[tid] = gb.x; sgy1[tid] = gb.y; sgx2[tid] = gb.z; sgy2[tid] = gb.w;
        float gcx = __fmul_rn(__fadd_rn(gb.x, gb.z), 0.5f);   // /2.0 exact
        float gcy = __fmul_rn(__fadd_rn(gb.y, gb.w), 0.5f);
        sglx[tid] = __fsub_rn(gcx, 2.5f); sghx[tid] = __fadd_rn(gcx, 2.5f);
        sgly[tid] = __fsub_rn(gcy, 2.5f); sghy[tid] = __fadd_rn(gcy, 2.5f);
        sgsx[tid] = __fadd_rn(gb.x, gb.z); sgsy[tid] = __fadd_rn(gb.y, gb.w);
        float w2 = __fsub_rn(gb.z, gb.x);
        float h2 = __fadd_rn(__fsub_rn(gb.w, gb.y), EPSV);
        swh[tid] = __fmul_rn(w2, h2);
        sat[tid] = atanf(__fdiv_rn(w2, h2));
        slab[tid] = glabels[b * GG + tid];
    }
    __syncthreads();

    int a = blockIdx.x * blockDim.x + tid;
    if (a >= AA) return;

    float4 pb = reinterpret_cast<const float4*>(pboxes)[(size_t)b * AA + a];
    float px1 = pb.x, py1 = pb.y, px2 = pb.z, py2 = pb.w;
    float w1   = __fsub_rn(px2, px1);
    float h1   = __fadd_rn(__fsub_rn(py2, py1), EPSV);
    float w1h1 = __fmul_rn(w1, h1);
    float pcx  = __fmul_rn(__fadd_rn(px1, px2), 0.5f);
    float pcy  = __fmul_rn(__fadd_rn(py1, py2), 0.5f);
    float atP  = g_atanP[b * AA + a];
    float Sv   = g_S[b * AA + a];
    const float* dbase = g_delta + (size_t)b * NCLS * AA + a;
    float* outp = costOut + (size_t)b * GG * AA + a;

#pragma unroll 4
    for (int g = 0; g < GG; g++) {
        float gx1 = sgx1[g], gy1 = sgy1[g], gx2 = sgx2[g], gy2 = sgy2[g];
        // intersection / union / iou
        float iw    = fmaxf(__fsub_rn(fminf(px2, gx2), fmaxf(px1, gx1)), 0.0f);
        float ih    = fmaxf(__fsub_rn(fminf(py2, gy2), fmaxf(py1, gy1)), 0.0f);
        float inter = __fmul_rn(iw, ih);
        float uni   = __fadd_rn(__fsub_rn(__fadd_rn(w1h1, swh[g]), inter), EPSV);
        float iou   = __fdiv_rn(inter, uni);
        // enclosing box diagonal^2
        float cw = __fsub_rn(fmaxf(px2, gx2), fminf(px1, gx1));
        float ch = __fsub_rn(fmaxf(py2, gy2), fminf(py1, gy1));
        float c2 = __fadd_rn(__fadd_rn(__fmul_rn(cw, cw), __fmul_rn(ch, ch)), EPSV);
        // center distance^2 / 4  (left-assoc subs as in reference)
        float dx = __fsub_rn(__fsub_rn(sgsx[g], px1), px2);
        float dy = __fsub_rn(__fsub_rn(sgsy[g], py1), py2);
        float d2 = __fmul_rn(__fadd_rn(__fmul_rn(dx, dx), __fmul_rn(dy, dy)), 0.25f); // /4 exact
        // aspect term
        float t = __fsub_rn(sat[g], atP);
        float v = __fmul_rn(0.4052847345693511f, __fmul_rn(t, t));
        float alpha = __fdiv_rn(v, __fadd_rn(__fsub_rn(v, iou), 1.0f));  // f32(1+1e-9)==1.0f
        float ciou  = __fsub_rn(iou, __fadd_rn(__fdiv_rn(d2, c2), __fmul_rn(v, alpha)));
        // class cost (coalesced gather from [b,c,a])
        float dl  = __ldg(dbase + (size_t)slab[g] * AA);
        float cls = __fadd_rn(Sv, dl);
        // candidate mask (exact f32 comparisons, both sides computed identically)
        bool both = (pcx > gx1) & (pcy > gy1) & (gx2 > pcx) & (gy2 > pcy) &
                    (pcx > sglx[g]) & (pcy > sgly[g]) & (sghx[g] > pcx) & (sghy[g] > pcy);
        float cost = __fadd_rn(__fadd_rn(cls, __fmul_rn(3.0f, ciou)), both ? 0.0f : BIGV);
        outp[(size_t)g * AA] = cost;
    }
}

// ---------------- K3: top-10 smallest per (b,g) row (ties -> lowest index) ----------------
__global__ void k3_topk(const float* __restrict__ costOut) {
    int bg = blockIdx.x;  // b*GG + g
    const float* rowp = costOut + (size_t)bg * AA;
    int tid = threadIdx.x;
    int lane = tid & 31, wid = tid >> 5;

    unsigned long long arr[TOPK];
#pragma unroll
    for (int i = 0; i < TOPK; i++) arr[i] = ~0ull;

    for (int i = tid; i < AA; i += blockDim.x) {
        float c = rowp[i];
        unsigned long long k = ((unsigned long long)encf(c) << 32) | (unsigned)i;
        if (k < arr[TOPK - 1]) {
            arr[TOPK - 1] = k;
#pragma unroll
            for (int j = TOPK - 1; j > 0; j--) {
                if (arr[j] < arr[j - 1]) {
                    unsigned long long tmp = arr[j]; arr[j] = arr[j - 1]; arr[j - 1] = tmp;
                }
            }
        }
    }

    __shared__ unsigned long long warpTop[8 * TOPK];
    int head = 0;
    for (int r = 0; r < TOPK; r++) {
        unsigned long long v = (head < TOPK) ? arr[head] : ~0ull;
        unsigned long long m = v;
#pragma unroll
        for (int off = 16; off > 0; off >>= 1) {
            unsigned long long o = __shfl_xor_sync(0xffffffffu, m, off);
            m = (o < m) ? o : m;
        }
        unsigned ball = __ballot_sync(0xffffffffu, v == m);
        int w = __ffs(ball) - 1;
        if (lane == w) head++;
        if (lane == 0) warpTop[wid * TOPK + r] = m;
    }
    __syncthreads();

    if (wid == 0) {
        unsigned long long a3[3];
#pragma unroll
        for (int j = 0; j < 3; j++) {
            int idx = lane + j * 32;
            a3[j] = (idx < 8 * TOPK) ? warpTop[idx] : ~0ull;
        }
        if (a3[1] < a3[0]) { unsigned long long t = a3[0]; a3[0] = a3[1]; a3[1] = t; }
        if (a3[2] < a3[1]) { unsigned long long t = a3[1]; a3[1] = a3[2]; a3[2] = t; }
        if (a3[1] < a3[0]) { unsigned long long t = a3[0]; a3[0] = a3[1]; a3[1] = t; }
        int h = 0;
        for (int r = 0; r < TOPK; r++) {
            unsigned long long v = (h < 3) ? a3[h] : ~0ull;
            unsigned long long m = v;
#pragma unroll
            for (int off = 16; off > 0; off >>= 1) {
                unsigned long long o = __shfl_xor_sync(0xffffffffu, m, off);
                m = (o < m) ? o : m;
            }
            unsigned ball = __ballot_sync(0xffffffffu, v == m);
            int w = __ffs(ball) - 1;
            if (lane == w) h++;
            if (lane == 0) {
                g_topidx[bg * TOPK + r]  = (int)(m & 0xffffffffu);
                g_topcost[bg * TOPK + r] = decf((unsigned)(m >> 32));
            }
        }
    }
}

// ---------------- K4a: scatter counts + argmin keys (mask read as 4-byte nonzero) ----------------
__global__ void k4a_scatter(const int* __restrict__ mask) {
    int t = blockIdx.x * blockDim.x + threadIdx.x;
    if (t >= BSZ * GG * TOPK) return;
    int bg = t / TOPK;
    int g  = bg % GG;
    int b  = bg / GG;
    if (mask[bg] == 0) return;
    int a = g_topidx[t];
    float c = g_topcost[t];
    atomicAdd(&g_cnt[b * AA + a], 1);
    unsigned long long k = ((unsigned long long)encf(c) << 32) | (unsigned)g;
    atomicMin(&g_pick[b * AA + a], k);
}

// ---------------- K4b: write final (sparse scatter) ----------------
__global__ void k4b_final(const int* __restrict__ mask, float* __restrict__ finalOut) {
    int t = blockIdx.x * blockDim.x + threadIdx.x;
    if (t >= BSZ * GG * TOPK) return;
    int bg = t / TOPK;
    int g  = bg % GG;
    int b  = bg / GG;
    if (mask[bg] == 0) return;
    int a = g_topidx[t];
    int c = g_cnt[b * AA + a];
    bool on;
    if (c > 1) {
        unsigned pg = (unsigned)(g_pick[b * AA + a] & 0xffffffffu);
        on = (pg == (unsigned)g);
    } else {
        on = true;
    }
    if (on) finalOut[(size_t)bg * AA + a] = 1.0f;
}

// ---------------- launch ----------------
extern "C" void kernel_launch(void* const* d_in, const int* in_sizes, int n_in,
                              void* d_out, int out_size) {
    const float* pboxes  = (const float*)d_in[0];
    const float* gboxes  = (const float*)d_in[1];
    const int*   maskgt  = (const int*)d_in[2];    // bool -> 4-byte (int32 or float32): nonzero test
    const float* scores  = (const float*)d_in[3];
    const int*   glabels = (const int*)d_in[4];

    const size_t N = (size_t)BSZ * GG * AA;
    float* finalOut = (float*)d_out;
    float* costOut  = finalOut + N;

    cudaMemsetAsync(d_out, 0, N * sizeof(float));
    k0_init<<<(BSZ * AA + 255) / 256, 256>>>();

    dim3 gridK1(AA / 8, BSZ);          // one warp per anchor, 8 warps/block
    k1_prep<<<gridK1, 256>>>(scores, pboxes);

    dim3 gridK2((AA + 255) / 256, BSZ);
    k2_cost<<<gridK2, 256>>>(pboxes, gboxes, glabels, costOut);

    k3_topk<<<BSZ * GG, 256>>>(costOut);

    int tot = BSZ * GG * TOPK;
    k4a_scatter<<<(tot + 255) / 256, 256>>>(maskgt);
    k4b_final<<<(tot + 255) / 256, 256>>>(maskgt, finalOut);
}